// round 5
// baseline (speedup 1.0000x reference)
#include <cuda_runtime.h>
#include <cstdint>

#define Bb 256
#define Tt 1024
#define Vv 128
#define Hh 128

// Scratch (no allocations allowed).
__device__ unsigned char g_symbols[Bb * Tt];
__device__ float g_WihT[127 * Hh];
__device__ int g_len[Bb];

// ---------------------------------------------------------------------------
// Kernel 0: lengths. x[b,t,0] == 1.0 iff symbol==0 (pad). length = first pad.
// Reads only 1 float per (b,t): 256K loads -> ~8MB of sectors.
// ---------------------------------------------------------------------------
__global__ void len_kernel(const float* __restrict__ x) {
    __shared__ int smin;
    const int b = blockIdx.x;
    if (threadIdx.x == 0) smin = Tt;
    __syncthreads();
    int local = Tt;
    for (int t = threadIdx.x; t < Tt; t += 128) {
        float v = __ldcs(x + ((size_t)b * Tt + t) * Vv);
        if (v > 0.5f && t < local) local = t;
    }
#pragma unroll
    for (int o = 16; o; o >>= 1) {
        int other = __shfl_xor_sync(0xffffffffu, local, o);
        local = min(local, other);
    }
    if ((threadIdx.x & 31) == 0) atomicMin(&smin, local);
    __syncthreads();
    if (threadIdx.x == 0) g_len[b] = smin;
}

// ---------------------------------------------------------------------------
// Kernel 1: extract symbol index from one-hot rows. Warp per (b,t) row.
// Skips rows past length[b] (symbol irrelevant there -> write 0).
// ---------------------------------------------------------------------------
__global__ void sym_kernel(const float* __restrict__ x) {
    int row  = blockIdx.x * 8 + (threadIdx.x >> 5);
    int lane = threadIdx.x & 31;
    int b = row >> 10;        // row / Tt
    int t = row & (Tt - 1);
    if (t >= g_len[b]) {
        if (lane == 0) g_symbols[row] = 0;
        return;
    }
    float4 v = __ldcs(reinterpret_cast<const float4*>(x + (size_t)row * Vv) + lane);
    int idx = 0;
    if (v.x > 0.5f) idx = lane * 4 + 0;
    if (v.y > 0.5f) idx = lane * 4 + 1;
    if (v.z > 0.5f) idx = lane * 4 + 2;
    if (v.w > 0.5f) idx = lane * 4 + 3;
#pragma unroll
    for (int o = 16; o; o >>= 1) idx += __shfl_xor_sync(0xffffffffu, idx, o);
    if (lane == 0) g_symbols[row] = (unsigned char)idx;
}

// ---------------------------------------------------------------------------
// Kernel 2: transpose W_ih (H=128, V-1=127) -> g_WihT[f*128 + h].
// ---------------------------------------------------------------------------
__global__ void transpose_kernel(const float* __restrict__ W_ih) {
    int f = blockIdx.x;    // 0..126
    int h = threadIdx.x;   // 0..127
    g_WihT[f * Hh + h] = W_ih[h * 127 + f];
}

// Packed dual-lane fp32 ops (Blackwell f32x2).
#define FMA2(d, a, b, c) \
    asm("fma.rn.f32x2 %0, %1, %2, %3;" : "=l"(d) : "l"(a), "l"(b), "l"(c))
#define ADD2(d, a, b) \
    asm("add.rn.f32x2 %0, %1, %2;" : "=l"(d) : "l"(a), "l"(b))
#define PACK2(d, lo, hi) \
    asm("mov.b64 %0, {%1, %2};" : "=l"(d) : "f"(lo), "f"(hi))

// ---------------------------------------------------------------------------
// Kernel 3: the RNN. One CTA per batch element, 128 threads; thread i owns
// h[i], W_hh row i lives in 64 packed-u64 registers. 4 independent packed
// accumulators break the FMA dependency chain (16 deps instead of 64).
// ---------------------------------------------------------------------------
__global__ __launch_bounds__(128, 2) void rnn_kernel(
    const float* __restrict__ W_hh,
    const float* __restrict__ b_ih,
    const float* __restrict__ b_hh,
    const float* __restrict__ W_out,
    const float* __restrict__ b_out,
    float* __restrict__ out)
{
    __shared__ __align__(16) float hb[2][Hh];
    __shared__ __align__(16) unsigned char ssym[Tt];
    __shared__ float red[2][Hh];

    const int b   = blockIdx.x;
    const int tid = threadIdx.x;

    // Stage this row's symbols into shared (1 KB).
    {
        const uint4* src = reinterpret_cast<const uint4*>(g_symbols + (size_t)b * Tt);
        uint4* dst = reinterpret_cast<uint4*>(ssym);
        for (int i = tid; i < Tt / 16; i += 128) dst[i] = src[i];
    }

    // W_hh row tid -> 64 packed f32x2 registers.
    unsigned long long w2[64];
    {
        const ulonglong2* wr = reinterpret_cast<const ulonglong2*>(W_hh + (size_t)tid * Hh);
#pragma unroll
        for (int c = 0; c < 32; c++) {
            ulonglong2 u = wr[c];
            w2[2 * c]     = u.x;
            w2[2 * c + 1] = u.y;
        }
    }

    const float bsum = b_ih[tid] + b_hh[tid];
    hb[0][tid] = 0.0f;
    __syncthreads();

    int   p = 0;
    int   t = 0;
    int   s = ssym[0];
    float pre = (s > 0) ? g_WihT[(s - 1) * Hh + tid] : 0.0f;

    while (s > 0) {
        const ulonglong2* h2 = reinterpret_cast<const ulonglong2*>(hb[p]);
        unsigned long long a0, a1, a2, a3;
        PACK2(a0, pre + bsum, 0.0f);
        a1 = 0; a2 = 0; a3 = 0;
#pragma unroll
        for (int c = 0; c < 16; c++) {
            ulonglong2 u = h2[2 * c];       // broadcast LDS.128
            ulonglong2 v = h2[2 * c + 1];   // broadcast LDS.128
            FMA2(a0, w2[4 * c + 0], u.x, a0);
            FMA2(a1, w2[4 * c + 1], u.y, a1);
            FMA2(a2, w2[4 * c + 2], v.x, a2);
            FMA2(a3, w2[4 * c + 3], v.y, a3);
        }
        ADD2(a0, a0, a1);
        ADD2(a2, a2, a3);
        ADD2(a0, a0, a2);
        float z = __uint_as_float((unsigned)a0)
                + __uint_as_float((unsigned)(a0 >> 32));
        // tanh(z) = 1 - 2/(exp(2z)+1)
        float e  = __expf(2.0f * z);
        float hn = 1.0f - __fdividef(2.0f, e + 1.0f);

        // Prefetch next step's symbol + pre before the barrier.
        t++;
        int sn = (t < Tt) ? (int)ssym[t] : 0;
        float pren = (sn > 0) ? g_WihT[(sn - 1) * Hh + tid] : 0.0f;

        hb[p ^ 1][tid] = hn;
        __syncthreads();
        p ^= 1;
        s = sn;
        pre = pren;
    }

    // Epilogue: h_last is in hb[p].
    float hv = hb[p][tid];
    out[2 * Bb + b * Hh + tid] = hv;               // hidden (1,B,H) at offset 512
    red[0][tid] = W_out[tid] * hv;                 // W_out row 0
    red[1][tid] = W_out[Hh + tid] * hv;            // W_out row 1
    __syncthreads();
    if (tid == 0) {
        float l0 = b_out[0], l1 = b_out[1];
#pragma unroll 8
        for (int i = 0; i < Hh; i++) { l0 += red[0][i]; l1 += red[1][i]; }
        float m  = fmaxf(l0, l1);
        float e0 = __expf(l0 - m), e1 = __expf(l1 - m);
        float inv = __fdividef(1.0f, e0 + e1);
        out[b * 2 + 0] = e0 * inv;                 // fed (B,2) at offset 0
        out[b * 2 + 1] = e1 * inv;
    }
}

// ---------------------------------------------------------------------------
extern "C" void kernel_launch(void* const* d_in, const int* in_sizes, int n_in,
                              void* d_out, int out_size) {
    (void)in_sizes; (void)n_in; (void)out_size;
    const float* x     = (const float*)d_in[0];
    const float* W_ih  = (const float*)d_in[1];
    const float* W_hh  = (const float*)d_in[2];
    const float* b_ih  = (const float*)d_in[3];
    const float* b_hh  = (const float*)d_in[4];
    const float* W_out = (const float*)d_in[5];
    const float* b_out = (const float*)d_in[6];
    float* out = (float*)d_out;

    len_kernel<<<Bb, 128>>>(x);
    sym_kernel<<<(Bb * Tt) / 8, 256>>>(x);
    transpose_kernel<<<127, 128>>>(W_ih);
    rnn_kernel<<<Bb, 128>>>(W_hh, b_ih, b_hh, W_out, b_out, out);
}

// round 7
// speedup vs baseline: 1.2427x; 1.2427x over previous
#include <cuda_runtime.h>
#include <cstdint>

#define Bb 256
#define Tt 1024
#define Vv 128
#define Hh 128
#define NSM 152          // GB300 sm_103a active SMs
#define NSOLO (Bb - NSM) // 104 paired bids -> 48 solo bids (104..151)

// Scratch (no allocations allowed).
__device__ unsigned char g_symbols[Bb * Tt];
__device__ float g_WihT[127 * Hh];
__device__ int g_len[Bb];
__device__ int g_assign[Bb];   // bid -> batch element

// ---------------------------------------------------------------------------
// Kernel 0: lengths. x[b,t,0] == 1.0 iff symbol==0 (pad). length = first pad.
// ---------------------------------------------------------------------------
__global__ void len_kernel(const float* __restrict__ x) {
    __shared__ int smin;
    const int b = blockIdx.x;
    if (threadIdx.x == 0) smin = Tt;
    __syncthreads();
    int local = Tt;
    for (int t = threadIdx.x; t < Tt; t += 128) {
        float v = __ldcs(x + ((size_t)b * Tt + t) * Vv);
        if (v > 0.5f && t < local) local = t;
    }
#pragma unroll
    for (int o = 16; o; o >>= 1) {
        int other = __shfl_xor_sync(0xffffffffu, local, o);
        local = min(local, other);
    }
    if ((threadIdx.x & 31) == 0) atomicMin(&smin, local);
    __syncthreads();
    if (threadIdx.x == 0) g_len[b] = smin;
}

// ---------------------------------------------------------------------------
// Kernel 0b: length-aware CTA->SM schedule.
// Classic placement: smid = LUT[bid % NSM]; bids b and b+NSM co-resident.
// Bids NSM-NSOLO.. (104..151) have no partner -> give them the longest items.
// Pair the rest anti-sorted so co-resident lengths sum ~constant.
// ---------------------------------------------------------------------------
__global__ void schedule_kernel() {
    __shared__ int slen[Bb];
    int b = threadIdx.x;           // 256 threads
    slen[b] = g_len[b];
    __syncthreads();
    int Lb = slen[b];
    int rank = 0;
#pragma unroll 8
    for (int j = 0; j < Bb; j++) {
        int Lj = slen[j];
        rank += (Lj > Lb) || (Lj == Lb && j < b);
    }
    int slot;
    if (rank < NSOLO)            slot = (NSM - NSOLO) + rank;   // 104..151 solo
    else if (rank < NSM)         slot = rank - NSOLO;           // 0..103
    else                         slot = (Bb - 1 - rank) + NSM;  // 152..255
    g_assign[slot] = b;
}

// ---------------------------------------------------------------------------
// Kernel 1: extract symbol index from one-hot rows. Warp per (b,t) row.
// ---------------------------------------------------------------------------
__global__ void sym_kernel(const float* __restrict__ x) {
    int row  = blockIdx.x * 8 + (threadIdx.x >> 5);
    int lane = threadIdx.x & 31;
    int b = row >> 10;        // row / Tt
    int t = row & (Tt - 1);
    if (t >= g_len[b]) {
        if (lane == 0) g_symbols[row] = 0;
        return;
    }
    float4 v = __ldcs(reinterpret_cast<const float4*>(x + (size_t)row * Vv) + lane);
    int idx = 0;
    if (v.x > 0.5f) idx = lane * 4 + 0;
    if (v.y > 0.5f) idx = lane * 4 + 1;
    if (v.z > 0.5f) idx = lane * 4 + 2;
    if (v.w > 0.5f) idx = lane * 4 + 3;
#pragma unroll
    for (int o = 16; o; o >>= 1) idx += __shfl_xor_sync(0xffffffffu, idx, o);
    if (lane == 0) g_symbols[row] = (unsigned char)idx;
}

// ---------------------------------------------------------------------------
// Kernel 2: transpose W_ih (H=128, V-1=127) -> g_WihT[f*128 + h].
// ---------------------------------------------------------------------------
__global__ void transpose_kernel(const float* __restrict__ W_ih) {
    int f = blockIdx.x;    // 0..126
    int h = threadIdx.x;   // 0..127
    g_WihT[f * Hh + h] = W_ih[h * 127 + f];
}

// Packed dual-lane fp32 ops (Blackwell f32x2).
#define FMA2(d, a, b, c) \
    asm("fma.rn.f32x2 %0, %1, %2, %3;" : "=l"(d) : "l"(a), "l"(b), "l"(c))
#define ADD2(d, a, b) \
    asm("add.rn.f32x2 %0, %1, %2;" : "=l"(d) : "l"(a), "l"(b))
#define PACK2(d, lo, hi) \
    asm("mov.b64 %0, {%1, %2};" : "=l"(d) : "f"(lo), "f"(hi))

// ---------------------------------------------------------------------------
// Kernel 3: the RNN. One CTA per (scheduled) batch element, 128 threads;
// thread i owns h[i], W_hh row i in 64 packed-u64 registers.
// ---------------------------------------------------------------------------
__global__ __launch_bounds__(128, 2) void rnn_kernel(
    const float* __restrict__ W_hh,
    const float* __restrict__ b_ih,
    const float* __restrict__ b_hh,
    const float* __restrict__ W_out,
    const float* __restrict__ b_out,
    float* __restrict__ out)
{
    __shared__ __align__(16) float hb[2][Hh];
    __shared__ __align__(16) unsigned char ssym[Tt];
    __shared__ float red[2][Hh];

    const int b   = g_assign[blockIdx.x];
    const int tid = threadIdx.x;

    // Stage this row's symbols into shared (1 KB).
    {
        const uint4* src = reinterpret_cast<const uint4*>(g_symbols + (size_t)b * Tt);
        uint4* dst = reinterpret_cast<uint4*>(ssym);
        for (int i = tid; i < Tt / 16; i += 128) dst[i] = src[i];
    }

    // W_hh row tid -> 64 packed f32x2 registers.
    unsigned long long w2[64];
    {
        const ulonglong2* wr = reinterpret_cast<const ulonglong2*>(W_hh + (size_t)tid * Hh);
#pragma unroll
        for (int c = 0; c < 32; c++) {
            ulonglong2 u = wr[c];
            w2[2 * c]     = u.x;
            w2[2 * c + 1] = u.y;
        }
    }

    const float bsum = b_ih[tid] + b_hh[tid];
    hb[0][tid] = 0.0f;
    __syncthreads();

    int   p = 0;
    int   t = 0;
    int   s = ssym[0];
    float pre = (s > 0) ? g_WihT[(s - 1) * Hh + tid] : 0.0f;

    while (s > 0) {
        const ulonglong2* h2 = reinterpret_cast<const ulonglong2*>(hb[p]);
        unsigned long long a0, a1, a2, a3;
        PACK2(a0, pre + bsum, 0.0f);
        a1 = 0; a2 = 0; a3 = 0;
#pragma unroll
        for (int c = 0; c < 16; c++) {
            ulonglong2 u = h2[2 * c];       // broadcast LDS.128
            ulonglong2 v = h2[2 * c + 1];   // broadcast LDS.128
            FMA2(a0, w2[4 * c + 0], u.x, a0);
            FMA2(a1, w2[4 * c + 1], u.y, a1);
            FMA2(a2, w2[4 * c + 2], v.x, a2);
            FMA2(a3, w2[4 * c + 3], v.y, a3);
        }
        ADD2(a0, a0, a1);
        ADD2(a2, a2, a3);
        ADD2(a0, a0, a2);
        float z = __uint_as_float((unsigned)a0)
                + __uint_as_float((unsigned)(a0 >> 32));
        // tanh(z) = 1 - 2/(exp(2z)+1)
        float e  = __expf(2.0f * z);
        float hn = 1.0f - __fdividef(2.0f, e + 1.0f);

        // Prefetch next step's symbol + pre before the barrier.
        t++;
        int sn = (t < Tt) ? (int)ssym[t] : 0;
        float pren = (sn > 0) ? g_WihT[(sn - 1) * Hh + tid] : 0.0f;

        hb[p ^ 1][tid] = hn;
        __syncthreads();
        p ^= 1;
        s = sn;
        pre = pren;
    }

    // Epilogue: h_last is in hb[p].
    float hv = hb[p][tid];
    out[2 * Bb + b * Hh + tid] = hv;               // hidden (1,B,H) at offset 512
    red[0][tid] = W_out[tid] * hv;                 // W_out row 0
    red[1][tid] = W_out[Hh + tid] * hv;            // W_out row 1
    __syncthreads();
    if (tid == 0) {
        float l0 = b_out[0], l1 = b_out[1];
#pragma unroll 8
        for (int i = 0; i < Hh; i++) { l0 += red[0][i]; l1 += red[1][i]; }
        float m  = fmaxf(l0, l1);
        float e0 = __expf(l0 - m), e1 = __expf(l1 - m);
        float inv = __fdividef(1.0f, e0 + e1);
        out[b * 2 + 0] = e0 * inv;                 // fed (B,2) at offset 0
        out[b * 2 + 1] = e1 * inv;
    }
}

// ---------------------------------------------------------------------------
extern "C" void kernel_launch(void* const* d_in, const int* in_sizes, int n_in,
                              void* d_out, int out_size) {
    (void)in_sizes; (void)n_in; (void)out_size;
    const float* x     = (const float*)d_in[0];
    const float* W_ih  = (const float*)d_in[1];
    const float* W_hh  = (const float*)d_in[2];
    const float* b_ih  = (const float*)d_in[3];
    const float* b_hh  = (const float*)d_in[4];
    const float* W_out = (const float*)d_in[5];
    const float* b_out = (const float*)d_in[6];
    float* out = (float*)d_out;

    len_kernel<<<Bb, 128>>>(x);
    schedule_kernel<<<1, Bb>>>();
    sym_kernel<<<(Bb * Tt) / 8, 256>>>(x);
    transpose_kernel<<<127, 128>>>(W_ih);
    rnn_kernel<<<Bb, 128>>>(W_hh, b_ih, b_hh, W_out, b_out, out);
}